// round 12
// baseline (speedup 1.0000x reference)
#include <cuda_runtime.h>
#include <cuda_bf16.h>
#include <cstdint>

#define B_ROWS  16384
#define IN_DIM  1024
#define OUT_DIM 768

// ---------------- device scratch (allocation-free rule) ----------------
__device__ __align__(16) float         g_z[B_ROWS * OUT_DIM];      // 48 MB
__device__ __align__(16) __nv_bfloat16 g_xhi[B_ROWS * IN_DIM];     // 32 MB
__device__ __align__(16) __nv_bfloat16 g_xlo[B_ROWS * IN_DIM];     // 32 MB
__device__ __align__(16) __nv_bfloat16 g_whi[OUT_DIM * IN_DIM];    // 1.5 MB
__device__ __align__(16) __nv_bfloat16 g_wlo[OUT_DIM * IN_DIM];    // 1.5 MB

// ---------------- helpers ----------------
__device__ __forceinline__ uint32_t smem_u32(const void* p) {
    uint32_t a;
    asm("{ .reg .u64 t; cvta.to.shared.u64 t, %1; cvt.u32.u64 %0, t; }" : "=r"(a) : "l"(p));
    return a;
}
__device__ __forceinline__ void cp16(uint32_t dst, const void* src) {
    asm volatile("cp.async.cg.shared.global [%0], [%1], 16;" :: "r"(dst), "l"(src));
}
__device__ __forceinline__ void ldsm4(uint32_t* r, uint32_t addr) {
    asm volatile("ldmatrix.sync.aligned.m8n8.x4.shared.b16 {%0,%1,%2,%3}, [%4];"
                 : "=r"(r[0]), "=r"(r[1]), "=r"(r[2]), "=r"(r[3]) : "r"(addr));
}
__device__ __forceinline__ void mma16816(float* c, const uint32_t* a, const uint32_t* b) {
    asm volatile(
        "mma.sync.aligned.m16n8k16.row.col.f32.bf16.bf16.f32 "
        "{%0,%1,%2,%3}, {%4,%5,%6,%7}, {%8,%9}, {%0,%1,%2,%3};"
        : "+f"(c[0]), "+f"(c[1]), "+f"(c[2]), "+f"(c[3])
        : "r"(a[0]), "r"(a[1]), "r"(a[2]), "r"(a[3]), "r"(b[0]), "r"(b[1]));
}

__device__ __forceinline__ void split4(float4 v, __nv_bfloat162* hp, __nv_bfloat162* lp, int i) {
    __nv_bfloat16 h0 = __float2bfloat16_rn(v.x);
    __nv_bfloat16 h1 = __float2bfloat16_rn(v.y);
    __nv_bfloat16 h2 = __float2bfloat16_rn(v.z);
    __nv_bfloat16 h3 = __float2bfloat16_rn(v.w);
    __nv_bfloat16 l0 = __float2bfloat16_rn(v.x - __bfloat162float(h0));
    __nv_bfloat16 l1 = __float2bfloat16_rn(v.y - __bfloat162float(h1));
    __nv_bfloat16 l2 = __float2bfloat16_rn(v.z - __bfloat162float(h2));
    __nv_bfloat16 l3 = __float2bfloat16_rn(v.w - __bfloat162float(h3));
    hp[2 * i]     = __nv_bfloat162(h0, h1);
    hp[2 * i + 1] = __nv_bfloat162(h2, h3);
    lp[2 * i]     = __nv_bfloat162(l0, l1);
    lp[2 * i + 1] = __nv_bfloat162(l2, l3);
}

#define N4X (B_ROWS * IN_DIM / 4)
#define N4W (OUT_DIM * IN_DIM / 4)
__global__ __launch_bounds__(256) void split_all_kernel(const float* __restrict__ x,
                                                        const float* __restrict__ W) {
    int i = blockIdx.x * blockDim.x + threadIdx.x;
    if (i < N4X) {
        split4(((const float4*)x)[i], (__nv_bfloat162*)g_xhi, (__nv_bfloat162*)g_xlo, i);
    } else if (i < N4X + N4W) {
        int j = i - N4X;
        split4(((const float4*)W)[j], (__nv_bfloat162*)g_whi, (__nv_bfloat162*)g_wlo, j);
    }
}

// ---------------- bf16x3 GEMM via mma.sync ----------------
// CTA 128x128x16, 4 warps of 64x64, 3-stage cp.async pipeline, 48 KB smem.
// This round: software-pipelined fragment loads (A m+1 prefetched under mma m,
// cp.async issued between frag-load batches and the m-loop).
#define BK      16
#define KITERS  (IN_DIM / BK)       // 64
#define TILE_B  (128 * BK * 2)      // 4096 B per tile
#define STAGE_B (4 * TILE_B)        // Ahi, Alo, Bhi, Blo = 16 KB
#define STAGES  3
#define SMEM_DYN (STAGES * STAGE_B) // 49152 B = 48 KB (default limit)

// swizzled byte offset inside one tile: 32B rows, granule kg in 0..1
__device__ __forceinline__ uint32_t swz16(int row, int kg) {
    return (uint32_t)(row * 32 + ((kg ^ ((row >> 2) & 1)) << 4));
}

// 128 threads: each loads 2 granules of a 128-row tile
__device__ __forceinline__ void ld_tile(uint32_t dst, const __nv_bfloat16* src,
                                        int k0, int tid) {
#pragma unroll
    for (int i = 0; i < 2; i++) {
        int gid = tid + i * 128;        // 0..255
        int r   = gid >> 1;
        int kg  = gid & 1;
        cp16(dst + swz16(r, kg), src + (size_t)r * IN_DIM + k0 + kg * 8);
    }
}

__global__ __launch_bounds__(128, 2) void gemm_bf16x3_kernel() {
    extern __shared__ char dsm[];
    const int tid  = threadIdx.x;
    const int wid  = tid >> 5;
    const int lane = tid & 31;
    const int bm = blockIdx.y * 128;
    const int bn = blockIdx.x * 128;
    const int warpM = (wid >> 1) * 64;   // 0 or 64
    const int warpN = (wid & 1) * 64;    // 0 or 64

    const uint32_t sbase = smem_u32(dsm);

    const __nv_bfloat16* xh = g_xhi + (size_t)bm * IN_DIM;
    const __nv_bfloat16* xl = g_xlo + (size_t)bm * IN_DIM;
    const __nv_bfloat16* wh = g_whi + (size_t)bn * IN_DIM;
    const __nv_bfloat16* wl = g_wlo + (size_t)bn * IN_DIM;

    // prologue: fill stages 0 and 1
#pragma unroll
    for (int s = 0; s < 2; s++) {
        uint32_t sb = sbase + s * STAGE_B;
        ld_tile(sb + 0 * TILE_B, xh, s * BK, tid);
        ld_tile(sb + 1 * TILE_B, xl, s * BK, tid);
        ld_tile(sb + 2 * TILE_B, wh, s * BK, tid);
        ld_tile(sb + 3 * TILE_B, wl, s * BK, tid);
        asm volatile("cp.async.commit_group;" ::: "memory");
    }

    // acc[m-atom][n8-col][quad] : 4 x 8 x 4 = 128 fp32
    float acc[4][8][4];
#pragma unroll
    for (int m = 0; m < 4; m++)
#pragma unroll
        for (int n = 0; n < 8; n++)
#pragma unroll
            for (int q = 0; q < 4; q++) acc[m][n][q] = 0.f;

    // per-lane ldmatrix address components (m16n8k16 fragment maps)
    const int arow = warpM + (lane & 7) + ((lane >> 3) & 1) * 8;
    const int akg  = lane >> 4;
    const int brow = warpN + (lane & 7) + (lane >> 4) * 8;
    const int bkg  = (lane >> 3) & 1;

    for (int i = 0; i < KITERS; i++) {
        const uint32_t sb = sbase + (i % STAGES) * STAGE_B;

        if (i == KITERS - 1) asm volatile("cp.async.wait_group 0;" ::: "memory");
        else                 asm volatile("cp.async.wait_group 1;" ::: "memory");
        __syncthreads();

        const uint32_t As = sb + 0 * TILE_B;
        const uint32_t Al = sb + 1 * TILE_B;
        const uint32_t Bs = sb + 2 * TILE_B;
        const uint32_t Bl = sb + 3 * TILE_B;

        // 1) issue all B fragments + A(m=0) fragments first
        uint32_t bhi[4][4], blo[4][4];
#pragma unroll
        for (int na = 0; na < 4; na++) {
            int r = brow + na * 16;
            ldsm4(bhi[na], Bs + swz16(r, bkg));
            ldsm4(blo[na], Bl + swz16(r, bkg));
        }
        uint32_t ah[2][4], al[2][4];
        ldsm4(ah[0], As + swz16(arow, akg));
        ldsm4(al[0], Al + swz16(arow, akg));

        // 2) issue global prefetch while fragment LDSMs are in flight
        if (i + 2 < KITERS) {
            uint32_t pb = sbase + ((i + 2) % STAGES) * STAGE_B;
            const int kn = (i + 2) * BK;
            ld_tile(pb + 0 * TILE_B, xh, kn, tid);
            ld_tile(pb + 1 * TILE_B, xl, kn, tid);
            ld_tile(pb + 2 * TILE_B, wh, kn, tid);
            ld_tile(pb + 3 * TILE_B, wl, kn, tid);
            asm volatile("cp.async.commit_group;" ::: "memory");
        }

        // 3) m-loop: prefetch A(m+1) under mma(m)
#pragma unroll
        for (int m = 0; m < 4; m++) {
            const int cur = m & 1;
            if (m < 3) {
                int r = arow + (m + 1) * 16;
                ldsm4(ah[cur ^ 1], As + swz16(r, akg));
                ldsm4(al[cur ^ 1], Al + swz16(r, akg));
            }
#pragma unroll
            for (int na = 0; na < 4; na++)
#pragma unroll
                for (int h = 0; h < 2; h++) {
                    float* c = acc[m][na * 2 + h];
                    mma16816(c, ah[cur], &bhi[na][h * 2]);
                    mma16816(c, ah[cur], &blo[na][h * 2]);
                    mma16816(c, al[cur], &bhi[na][h * 2]);
                }
        }
    }

    // epilogue: direct fp32 stores to g_z
#pragma unroll
    for (int m = 0; m < 4; m++) {
        int row = bm + warpM + m * 16 + (lane >> 2);
#pragma unroll
        for (int n = 0; n < 8; n++) {
            int col = bn + warpN + n * 8 + (lane & 3) * 2;
            *(float2*)(g_z + (size_t)row * OUT_DIM + col) =
                make_float2(acc[m][n][0], acc[m][n][1]);
            *(float2*)(g_z + (size_t)(row + 8) * OUT_DIM + col) =
                make_float2(acc[m][n][2], acc[m][n][3]);
        }
    }
}

// ---------------------------------------------------------------------------
// Batched Householder QR (LAPACK geqrf/orgqr) of 256x3 matrices. (unchanged)
// ---------------------------------------------------------------------------
__device__ __forceinline__ float warp_sum(float v) {
#pragma unroll
    for (int o = 16; o > 0; o >>= 1) v += __shfl_xor_sync(0xffffffffu, v, o);
    return v;
}

__global__ __launch_bounds__(256) void qr_kernel(float* __restrict__ out) {
    const int warp = (blockIdx.x * blockDim.x + threadIdx.x) >> 5;
    const int lane = threadIdx.x & 31;
    if (warp >= B_ROWS) return;

    float4 buf[6];
    const float4* zp = (const float4*)(g_z + (size_t)warp * OUT_DIM) + lane * 6;
#pragma unroll
    for (int i = 0; i < 6; i++) buf[i] = zp[i];
    float* bf = (float*)buf;

    float Mv[8][3];
#pragma unroll
    for (int r = 0; r < 8; r++)
#pragma unroll
        for (int j = 0; j < 3; j++) Mv[r][j] = bf[r * 3 + j];

    const int gr0 = lane * 8;
    float tau[3];

#pragma unroll
    for (int k = 0; k < 3; k++) {
        float ss = 0.f;
#pragma unroll
        for (int r = 0; r < 8; r++) {
            int gr = gr0 + r;
            if (gr >= k) ss += Mv[r][k] * Mv[r][k];
        }
        ss = warp_sum(ss);
        float alpha = __shfl_sync(0xffffffffu, Mv[k][k], 0);
        float nrm = sqrtf(ss);
        float beta = (alpha >= 0.f) ? -nrm : nrm;
        float t = (nrm > 0.f) ? (beta - alpha) / beta : 0.f;
        tau[k] = t;
        float inv = (nrm > 0.f) ? 1.0f / (alpha - beta) : 0.f;
#pragma unroll
        for (int r = 0; r < 8; r++) {
            int gr = gr0 + r;
            if (gr > k) Mv[r][k] *= inv;
        }
#pragma unroll
        for (int j = 0; j < 3; j++) {
            if (j <= k) continue;
            float d = 0.f;
#pragma unroll
            for (int r = 0; r < 8; r++) {
                int gr = gr0 + r;
                if (gr > k)       d += Mv[r][k] * Mv[r][j];
                else if (gr == k) d += Mv[r][j];
            }
            d = warp_sum(d);
            float td = t * d;
#pragma unroll
            for (int r = 0; r < 8; r++) {
                int gr = gr0 + r;
                if (gr > k)       Mv[r][j] -= td * Mv[r][k];
                else if (gr == k) Mv[r][j] -= td;
            }
        }
    }

    float Q[8][3];
#pragma unroll
    for (int r = 0; r < 8; r++)
#pragma unroll
        for (int j = 0; j < 3; j++) Q[r][j] = (gr0 + r == j) ? 1.f : 0.f;

#pragma unroll
    for (int k = 2; k >= 0; k--) {
        float d[3];
#pragma unroll
        for (int j = 0; j < 3; j++) {
            float s = 0.f;
#pragma unroll
            for (int r = 0; r < 8; r++) {
                int gr = gr0 + r;
                if (gr > k)       s += Mv[r][k] * Q[r][j];
                else if (gr == k) s += Q[r][j];
            }
            d[j] = warp_sum(s) * tau[k];
        }
#pragma unroll
        for (int j = 0; j < 3; j++) {
#pragma unroll
            for (int r = 0; r < 8; r++) {
                int gr = gr0 + r;
                if (gr > k)       Q[r][j] -= d[j] * Mv[r][k];
                else if (gr == k) Q[r][j] -= d[j];
            }
        }
    }

#pragma unroll
    for (int r = 0; r < 8; r++)
#pragma unroll
        for (int j = 0; j < 3; j++) bf[r * 3 + j] = Q[r][j];
    float4* op = (float4*)(out + (size_t)warp * OUT_DIM) + lane * 6;
#pragma unroll
    for (int i = 0; i < 6; i++) op[i] = buf[i];
}

// ---------------------------------------------------------------------------
// kernel_launch: ONLY kernel launches — no runtime API calls of any kind.
// ---------------------------------------------------------------------------
extern "C" void kernel_launch(void* const* d_in, const int* in_sizes, int n_in,
                              void* d_out, int out_size) {
    const float* x = (const float*)d_in[0];   // (16384, 1024) fp32
    const float* W = (const float*)d_in[1];   // (768, 1024) fp32
    float* out = (float*)d_out;               // (16384, 768) fp32

    split_all_kernel<<<(N4X + N4W + 255) / 256, 256>>>(x, W);

    dim3 grid(OUT_DIM / 128, B_ROWS / 128);   // (6, 128)
    gemm_bf16x3_kernel<<<grid, 128, SMEM_DYN>>>();

    qr_kernel<<<2048, 256>>>(out);
}

// round 14
// speedup vs baseline: 1.0873x; 1.0873x over previous
#include <cuda_runtime.h>
#include <cuda_bf16.h>
#include <cstdint>

#define B_ROWS  16384
#define IN_DIM  1024
#define OUT_DIM 768

// ---------------- device scratch (allocation-free rule) ----------------
__device__ __align__(16) float         g_z[B_ROWS * OUT_DIM];      // 48 MB
__device__ __align__(16) __nv_bfloat16 g_xhi[B_ROWS * IN_DIM];     // 32 MB
__device__ __align__(16) __nv_bfloat16 g_xlo[B_ROWS * IN_DIM];     // 32 MB
__device__ __align__(16) __nv_bfloat16 g_whi[OUT_DIM * IN_DIM];    // 1.5 MB
__device__ __align__(16) __nv_bfloat16 g_wlo[OUT_DIM * IN_DIM];    // 1.5 MB

// ---------------- helpers ----------------
__device__ __forceinline__ uint32_t smem_u32(const void* p) {
    uint32_t a;
    asm("{ .reg .u64 t; cvta.to.shared.u64 t, %1; cvt.u32.u64 %0, t; }" : "=r"(a) : "l"(p));
    return a;
}
__device__ __forceinline__ void cp16(uint32_t dst, const void* src) {
    asm volatile("cp.async.cg.shared.global [%0], [%1], 16;" :: "r"(dst), "l"(src));
}
__device__ __forceinline__ void ldsm4(uint32_t* r, uint32_t addr) {
    asm volatile("ldmatrix.sync.aligned.m8n8.x4.shared.b16 {%0,%1,%2,%3}, [%4];"
                 : "=r"(r[0]), "=r"(r[1]), "=r"(r[2]), "=r"(r[3]) : "r"(addr));
}
__device__ __forceinline__ void mma16816(float* c, const uint32_t* a, const uint32_t* b) {
    asm volatile(
        "mma.sync.aligned.m16n8k16.row.col.f32.bf16.bf16.f32 "
        "{%0,%1,%2,%3}, {%4,%5,%6,%7}, {%8,%9}, {%0,%1,%2,%3};"
        : "+f"(c[0]), "+f"(c[1]), "+f"(c[2]), "+f"(c[3])
        : "r"(a[0]), "r"(a[1]), "r"(a[2]), "r"(a[3]), "r"(b[0]), "r"(b[1]));
}

__device__ __forceinline__ void split4(float4 v, __nv_bfloat162* hp, __nv_bfloat162* lp, int i) {
    __nv_bfloat16 h0 = __float2bfloat16_rn(v.x);
    __nv_bfloat16 h1 = __float2bfloat16_rn(v.y);
    __nv_bfloat16 h2 = __float2bfloat16_rn(v.z);
    __nv_bfloat16 h3 = __float2bfloat16_rn(v.w);
    __nv_bfloat16 l0 = __float2bfloat16_rn(v.x - __bfloat162float(h0));
    __nv_bfloat16 l1 = __float2bfloat16_rn(v.y - __bfloat162float(h1));
    __nv_bfloat16 l2 = __float2bfloat16_rn(v.z - __bfloat162float(h2));
    __nv_bfloat16 l3 = __float2bfloat16_rn(v.w - __bfloat162float(h3));
    hp[2 * i]     = __nv_bfloat162(h0, h1);
    hp[2 * i + 1] = __nv_bfloat162(h2, h3);
    lp[2 * i]     = __nv_bfloat162(l0, l1);
    lp[2 * i + 1] = __nv_bfloat162(l2, l3);
}

#define N4X (B_ROWS * IN_DIM / 4)
#define N4W (OUT_DIM * IN_DIM / 4)
__global__ __launch_bounds__(256) void split_all_kernel(const float* __restrict__ x,
                                                        const float* __restrict__ W) {
    int i = blockIdx.x * blockDim.x + threadIdx.x;
    if (i < N4X) {
        split4(((const float4*)x)[i], (__nv_bfloat162*)g_xhi, (__nv_bfloat162*)g_xlo, i);
    } else if (i < N4X + N4W) {
        int j = i - N4X;
        split4(((const float4*)W)[j], (__nv_bfloat162*)g_whi, (__nv_bfloat162*)g_wlo, j);
    }
}

// ---------------- bf16x3 GEMM via mma.sync ----------------
// CTA 128x128x16, 4 warps of 64x64, 3-stage cp.async pipeline, 48 KB smem.
// R11 skeleton (prefetch first), plus term-loop hoist: the 3 split terms are
// issued as 3 groups of 8 INDEPENDENT mmas instead of 3-deep same-accumulator
// RAW chains.
#define BK      16
#define KITERS  (IN_DIM / BK)       // 64
#define TILE_B  (128 * BK * 2)      // 4096 B per tile
#define STAGE_B (4 * TILE_B)        // Ahi, Alo, Bhi, Blo = 16 KB
#define STAGES  3
#define SMEM_DYN (STAGES * STAGE_B) // 49152 B = 48 KB (default limit)

// swizzled byte offset inside one tile: 32B rows, granule kg in 0..1
__device__ __forceinline__ uint32_t swz16(int row, int kg) {
    return (uint32_t)(row * 32 + ((kg ^ ((row >> 2) & 1)) << 4));
}

// 128 threads: each loads 2 granules of a 128-row tile
__device__ __forceinline__ void ld_tile(uint32_t dst, const __nv_bfloat16* src,
                                        int k0, int tid) {
#pragma unroll
    for (int i = 0; i < 2; i++) {
        int gid = tid + i * 128;        // 0..255
        int r   = gid >> 1;
        int kg  = gid & 1;
        cp16(dst + swz16(r, kg), src + (size_t)r * IN_DIM + k0 + kg * 8);
    }
}

__global__ __launch_bounds__(128, 2) void gemm_bf16x3_kernel() {
    extern __shared__ char dsm[];
    const int tid  = threadIdx.x;
    const int wid  = tid >> 5;
    const int lane = tid & 31;
    const int bm = blockIdx.y * 128;
    const int bn = blockIdx.x * 128;
    const int warpM = (wid >> 1) * 64;   // 0 or 64
    const int warpN = (wid & 1) * 64;    // 0 or 64

    const uint32_t sbase = smem_u32(dsm);

    const __nv_bfloat16* xh = g_xhi + (size_t)bm * IN_DIM;
    const __nv_bfloat16* xl = g_xlo + (size_t)bm * IN_DIM;
    const __nv_bfloat16* wh = g_whi + (size_t)bn * IN_DIM;
    const __nv_bfloat16* wl = g_wlo + (size_t)bn * IN_DIM;

    // prologue: fill stages 0 and 1
#pragma unroll
    for (int s = 0; s < 2; s++) {
        uint32_t sb = sbase + s * STAGE_B;
        ld_tile(sb + 0 * TILE_B, xh, s * BK, tid);
        ld_tile(sb + 1 * TILE_B, xl, s * BK, tid);
        ld_tile(sb + 2 * TILE_B, wh, s * BK, tid);
        ld_tile(sb + 3 * TILE_B, wl, s * BK, tid);
        asm volatile("cp.async.commit_group;" ::: "memory");
    }

    // acc[m-atom][n8-col][quad] : 4 x 8 x 4 = 128 fp32
    float acc[4][8][4];
#pragma unroll
    for (int m = 0; m < 4; m++)
#pragma unroll
        for (int n = 0; n < 8; n++)
#pragma unroll
            for (int q = 0; q < 4; q++) acc[m][n][q] = 0.f;

    // per-lane ldmatrix address components (m16n8k16 fragment maps)
    const int arow = warpM + (lane & 7) + ((lane >> 3) & 1) * 8;
    const int akg  = lane >> 4;
    const int brow = warpN + (lane & 7) + (lane >> 4) * 8;
    const int bkg  = (lane >> 3) & 1;

    for (int i = 0; i < KITERS; i++) {
        const uint32_t sb = sbase + (i % STAGES) * STAGE_B;

        if (i == KITERS - 1) asm volatile("cp.async.wait_group 0;" ::: "memory");
        else                 asm volatile("cp.async.wait_group 1;" ::: "memory");
        __syncthreads();

        // prefetch i+2 into the slot freed by i-1 (R11 ordering: prefetch first)
        if (i + 2 < KITERS) {
            uint32_t pb = sbase + ((i + 2) % STAGES) * STAGE_B;
            const int kn = (i + 2) * BK;
            ld_tile(pb + 0 * TILE_B, xh, kn, tid);
            ld_tile(pb + 1 * TILE_B, xl, kn, tid);
            ld_tile(pb + 2 * TILE_B, wh, kn, tid);
            ld_tile(pb + 3 * TILE_B, wl, kn, tid);
            asm volatile("cp.async.commit_group;" ::: "memory");
        }

        const uint32_t As = sb + 0 * TILE_B;
        const uint32_t Al = sb + 1 * TILE_B;
        const uint32_t Bs = sb + 2 * TILE_B;
        const uint32_t Bl = sb + 3 * TILE_B;

        // B fragments: 4 n-atoms x (hi,lo), resident for whole iter (32 regs)
        uint32_t bhi[4][4], blo[4][4];
#pragma unroll
        for (int na = 0; na < 4; na++) {
            int r = brow + na * 16;
            ldsm4(bhi[na], Bs + swz16(r, bkg));
            ldsm4(blo[na], Bl + swz16(r, bkg));
        }

#pragma unroll
        for (int m = 0; m < 4; m++) {
            uint32_t ah[4], al[4];
            int r = arow + m * 16;
            ldsm4(ah, As + swz16(r, akg));
            ldsm4(al, Al + swz16(r, akg));
            // term-hoisted: 3 groups of 8 independent mmas (no same-acc chains)
#pragma unroll
            for (int na = 0; na < 4; na++)
#pragma unroll
                for (int h = 0; h < 2; h++)
                    mma16816(acc[m][na * 2 + h], ah, &bhi[na][h * 2]);
#pragma unroll
            for (int na = 0; na < 4; na++)
#pragma unroll
                for (int h = 0; h < 2; h++)
                    mma16816(acc[m][na * 2 + h], ah, &blo[na][h * 2]);
#pragma unroll
            for (int na = 0; na < 4; na++)
#pragma unroll
                for (int h = 0; h < 2; h++)
                    mma16816(acc[m][na * 2 + h], al, &bhi[na][h * 2]);
        }
    }

    // epilogue: direct fp32 stores to g_z
#pragma unroll
    for (int m = 0; m < 4; m++) {
        int row = bm + warpM + m * 16 + (lane >> 2);
#pragma unroll
        for (int n = 0; n < 8; n++) {
            int col = bn + warpN + n * 8 + (lane & 3) * 2;
            *(float2*)(g_z + (size_t)row * OUT_DIM + col) =
                make_float2(acc[m][n][0], acc[m][n][1]);
            *(float2*)(g_z + (size_t)(row + 8) * OUT_DIM + col) =
                make_float2(acc[m][n][2], acc[m][n][3]);
        }
    }
}

// ---------------------------------------------------------------------------
// Batched Householder QR (LAPACK geqrf/orgqr) of 256x3 matrices. (unchanged)
// ---------------------------------------------------------------------------
__device__ __forceinline__ float warp_sum(float v) {
#pragma unroll
    for (int o = 16; o > 0; o >>= 1) v += __shfl_xor_sync(0xffffffffu, v, o);
    return v;
}

__global__ __launch_bounds__(256) void qr_kernel(float* __restrict__ out) {
    const int warp = (blockIdx.x * blockDim.x + threadIdx.x) >> 5;
    const int lane = threadIdx.x & 31;
    if (warp >= B_ROWS) return;

    float4 buf[6];
    const float4* zp = (const float4*)(g_z + (size_t)warp * OUT_DIM) + lane * 6;
#pragma unroll
    for (int i = 0; i < 6; i++) buf[i] = zp[i];
    float* bf = (float*)buf;

    float Mv[8][3];
#pragma unroll
    for (int r = 0; r < 8; r++)
#pragma unroll
        for (int j = 0; j < 3; j++) Mv[r][j] = bf[r * 3 + j];

    const int gr0 = lane * 8;
    float tau[3];

#pragma unroll
    for (int k = 0; k < 3; k++) {
        float ss = 0.f;
#pragma unroll
        for (int r = 0; r < 8; r++) {
            int gr = gr0 + r;
            if (gr >= k) ss += Mv[r][k] * Mv[r][k];
        }
        ss = warp_sum(ss);
        float alpha = __shfl_sync(0xffffffffu, Mv[k][k], 0);
        float nrm = sqrtf(ss);
        float beta = (alpha >= 0.f) ? -nrm : nrm;
        float t = (nrm > 0.f) ? (beta - alpha) / beta : 0.f;
        tau[k] = t;
        float inv = (nrm > 0.f) ? 1.0f / (alpha - beta) : 0.f;
#pragma unroll
        for (int r = 0; r < 8; r++) {
            int gr = gr0 + r;
            if (gr > k) Mv[r][k] *= inv;
        }
#pragma unroll
        for (int j = 0; j < 3; j++) {
            if (j <= k) continue;
            float d = 0.f;
#pragma unroll
            for (int r = 0; r < 8; r++) {
                int gr = gr0 + r;
                if (gr > k)       d += Mv[r][k] * Mv[r][j];
                else if (gr == k) d += Mv[r][j];
            }
            d = warp_sum(d);
            float td = t * d;
#pragma unroll
            for (int r = 0; r < 8; r++) {
                int gr = gr0 + r;
                if (gr > k)       Mv[r][j] -= td * Mv[r][k];
                else if (gr == k) Mv[r][j] -= td;
            }
        }
    }

    float Q[8][3];
#pragma unroll
    for (int r = 0; r < 8; r++)
#pragma unroll
        for (int j = 0; j < 3; j++) Q[r][j] = (gr0 + r == j) ? 1.f : 0.f;

#pragma unroll
    for (int k = 2; k >= 0; k--) {
        float d[3];
#pragma unroll
        for (int j = 0; j < 3; j++) {
            float s = 0.f;
#pragma unroll
            for (int r = 0; r < 8; r++) {
                int gr = gr0 + r;
                if (gr > k)       s += Mv[r][k] * Q[r][j];
                else if (gr == k) s += Q[r][j];
            }
            d[j] = warp_sum(s) * tau[k];
        }
#pragma unroll
        for (int j = 0; j < 3; j++) {
#pragma unroll
            for (int r = 0; r < 8; r++) {
                int gr = gr0 + r;
                if (gr > k)       Q[r][j] -= d[j] * Mv[r][k];
                else if (gr == k) Q[r][j] -= d[j];
            }
        }
    }

#pragma unroll
    for (int r = 0; r < 8; r++)
#pragma unroll
        for (int j = 0; j < 3; j++) bf[r * 3 + j] = Q[r][j];
    float4* op = (float4*)(out + (size_t)warp * OUT_DIM) + lane * 6;
#pragma unroll
    for (int i = 0; i < 6; i++) op[i] = buf[i];
}

// ---------------------------------------------------------------------------
// kernel_launch: ONLY kernel launches — no runtime API calls of any kind.
// ---------------------------------------------------------------------------
extern "C" void kernel_launch(void* const* d_in, const int* in_sizes, int n_in,
                              void* d_out, int out_size) {
    const float* x = (const float*)d_in[0];   // (16384, 1024) fp32
    const float* W = (const float*)d_in[1];   // (768, 1024) fp32
    float* out = (float*)d_out;               // (16384, 768) fp32

    split_all_kernel<<<(N4X + N4W + 255) / 256, 256>>>(x, W);

    dim3 grid(OUT_DIM / 128, B_ROWS / 128);   // (6, 128)
    gemm_bf16x3_kernel<<<grid, 128, SMEM_DYN>>>();

    qr_kernel<<<2048, 256>>>(out);
}

// round 17
// speedup vs baseline: 1.0979x; 1.0098x over previous
#include <cuda_runtime.h>
#include <cuda_bf16.h>
#include <cstdint>

#define B_ROWS  16384
#define IN_DIM  1024
#define OUT_DIM 768

// ---------------- device scratch (allocation-free rule) ----------------
__device__ __align__(16) float         g_z[B_ROWS * OUT_DIM];      // 48 MB
__device__ __align__(16) __nv_bfloat16 g_xhi[B_ROWS * IN_DIM];     // 32 MB
__device__ __align__(16) __nv_bfloat16 g_xlo[B_ROWS * IN_DIM];     // 32 MB
__device__ __align__(16) __nv_bfloat16 g_whi[OUT_DIM * IN_DIM];    // 1.5 MB
__device__ __align__(16) __nv_bfloat16 g_wlo[OUT_DIM * IN_DIM];    // 1.5 MB

// ---------------- helpers ----------------
__device__ __forceinline__ uint32_t smem_u32(const void* p) {
    uint32_t a;
    asm("{ .reg .u64 t; cvta.to.shared.u64 t, %1; cvt.u32.u64 %0, t; }" : "=r"(a) : "l"(p));
    return a;
}
__device__ __forceinline__ void cp16(uint32_t dst, const void* src) {
    asm volatile("cp.async.cg.shared.global [%0], [%1], 16;" :: "r"(dst), "l"(src));
}
__device__ __forceinline__ void ldsm4(uint32_t* r, uint32_t addr) {
    asm volatile("ldmatrix.sync.aligned.m8n8.x4.shared.b16 {%0,%1,%2,%3}, [%4];"
                 : "=r"(r[0]), "=r"(r[1]), "=r"(r[2]), "=r"(r[3]) : "r"(addr));
}
__device__ __forceinline__ void mma16816(float* c, const uint32_t* a, const uint32_t* b) {
    asm volatile(
        "mma.sync.aligned.m16n8k16.row.col.f32.bf16.bf16.f32 "
        "{%0,%1,%2,%3}, {%4,%5,%6,%7}, {%8,%9}, {%0,%1,%2,%3};"
        : "+f"(c[0]), "+f"(c[1]), "+f"(c[2]), "+f"(c[3])
        : "r"(a[0]), "r"(a[1]), "r"(a[2]), "r"(a[3]), "r"(b[0]), "r"(b[1]));
}

__device__ __forceinline__ void split4(float4 v, __nv_bfloat162* hp, __nv_bfloat162* lp, int i) {
    __nv_bfloat16 h0 = __float2bfloat16_rn(v.x);
    __nv_bfloat16 h1 = __float2bfloat16_rn(v.y);
    __nv_bfloat16 h2 = __float2bfloat16_rn(v.z);
    __nv_bfloat16 h3 = __float2bfloat16_rn(v.w);
    __nv_bfloat16 l0 = __float2bfloat16_rn(v.x - __bfloat162float(h0));
    __nv_bfloat16 l1 = __float2bfloat16_rn(v.y - __bfloat162float(h1));
    __nv_bfloat16 l2 = __float2bfloat16_rn(v.z - __bfloat162float(h2));
    __nv_bfloat16 l3 = __float2bfloat16_rn(v.w - __bfloat162float(h3));
    hp[2 * i]     = __nv_bfloat162(h0, h1);
    hp[2 * i + 1] = __nv_bfloat162(h2, h3);
    lp[2 * i]     = __nv_bfloat162(l0, l1);
    lp[2 * i + 1] = __nv_bfloat162(l2, l3);
}

#define N4X (B_ROWS * IN_DIM / 4)
#define N4W (OUT_DIM * IN_DIM / 4)
__global__ __launch_bounds__(256) void split_all_kernel(const float* __restrict__ x,
                                                        const float* __restrict__ W) {
    int i = blockIdx.x * blockDim.x + threadIdx.x;
    if (i < N4X) {
        split4(((const float4*)x)[i], (__nv_bfloat162*)g_xhi, (__nv_bfloat162*)g_xlo, i);
    } else if (i < N4X + N4W) {
        int j = i - N4X;
        split4(((const float4*)W)[j], (__nv_bfloat162*)g_whi, (__nv_bfloat162*)g_wlo, j);
    }
}

// ---------------- bf16x3 GEMM via mma.sync (unchanged from R14 best) ----------------
#define BK      16
#define KITERS  (IN_DIM / BK)       // 64
#define TILE_B  (128 * BK * 2)      // 4096 B per tile
#define STAGE_B (4 * TILE_B)        // Ahi, Alo, Bhi, Blo = 16 KB
#define STAGES  3
#define SMEM_DYN (STAGES * STAGE_B) // 49152 B = 48 KB (default limit)

__device__ __forceinline__ uint32_t swz16(int row, int kg) {
    return (uint32_t)(row * 32 + ((kg ^ ((row >> 2) & 1)) << 4));
}

__device__ __forceinline__ void ld_tile(uint32_t dst, const __nv_bfloat16* src,
                                        int k0, int tid) {
#pragma unroll
    for (int i = 0; i < 2; i++) {
        int gid = tid + i * 128;        // 0..255
        int r   = gid >> 1;
        int kg  = gid & 1;
        cp16(dst + swz16(r, kg), src + (size_t)r * IN_DIM + k0 + kg * 8);
    }
}

__global__ __launch_bounds__(128, 2) void gemm_bf16x3_kernel() {
    extern __shared__ char dsm[];
    const int tid  = threadIdx.x;
    const int wid  = tid >> 5;
    const int lane = tid & 31;
    const int bm = blockIdx.y * 128;
    const int bn = blockIdx.x * 128;
    const int warpM = (wid >> 1) * 64;
    const int warpN = (wid & 1) * 64;

    const uint32_t sbase = smem_u32(dsm);

    const __nv_bfloat16* xh = g_xhi + (size_t)bm * IN_DIM;
    const __nv_bfloat16* xl = g_xlo + (size_t)bm * IN_DIM;
    const __nv_bfloat16* wh = g_whi + (size_t)bn * IN_DIM;
    const __nv_bfloat16* wl = g_wlo + (size_t)bn * IN_DIM;

#pragma unroll
    for (int s = 0; s < 2; s++) {
        uint32_t sb = sbase + s * STAGE_B;
        ld_tile(sb + 0 * TILE_B, xh, s * BK, tid);
        ld_tile(sb + 1 * TILE_B, xl, s * BK, tid);
        ld_tile(sb + 2 * TILE_B, wh, s * BK, tid);
        ld_tile(sb + 3 * TILE_B, wl, s * BK, tid);
        asm volatile("cp.async.commit_group;" ::: "memory");
    }

    float acc[4][8][4];
#pragma unroll
    for (int m = 0; m < 4; m++)
#pragma unroll
        for (int n = 0; n < 8; n++)
#pragma unroll
            for (int q = 0; q < 4; q++) acc[m][n][q] = 0.f;

    const int arow = warpM + (lane & 7) + ((lane >> 3) & 1) * 8;
    const int akg  = lane >> 4;
    const int brow = warpN + (lane & 7) + (lane >> 4) * 8;
    const int bkg  = (lane >> 3) & 1;

    for (int i = 0; i < KITERS; i++) {
        const uint32_t sb = sbase + (i % STAGES) * STAGE_B;

        if (i == KITERS - 1) asm volatile("cp.async.wait_group 0;" ::: "memory");
        else                 asm volatile("cp.async.wait_group 1;" ::: "memory");
        __syncthreads();

        if (i + 2 < KITERS) {
            uint32_t pb = sbase + ((i + 2) % STAGES) * STAGE_B;
            const int kn = (i + 2) * BK;
            ld_tile(pb + 0 * TILE_B, xh, kn, tid);
            ld_tile(pb + 1 * TILE_B, xl, kn, tid);
            ld_tile(pb + 2 * TILE_B, wh, kn, tid);
            ld_tile(pb + 3 * TILE_B, wl, kn, tid);
            asm volatile("cp.async.commit_group;" ::: "memory");
        }

        const uint32_t As = sb + 0 * TILE_B;
        const uint32_t Al = sb + 1 * TILE_B;
        const uint32_t Bs = sb + 2 * TILE_B;
        const uint32_t Bl = sb + 3 * TILE_B;

        uint32_t bhi[4][4], blo[4][4];
#pragma unroll
        for (int na = 0; na < 4; na++) {
            int r = brow + na * 16;
            ldsm4(bhi[na], Bs + swz16(r, bkg));
            ldsm4(blo[na], Bl + swz16(r, bkg));
        }

#pragma unroll
        for (int m = 0; m < 4; m++) {
            uint32_t ah[4], al[4];
            int r = arow + m * 16;
            ldsm4(ah, As + swz16(r, akg));
            ldsm4(al, Al + swz16(r, akg));
#pragma unroll
            for (int na = 0; na < 4; na++)
#pragma unroll
                for (int h = 0; h < 2; h++)
                    mma16816(acc[m][na * 2 + h], ah, &bhi[na][h * 2]);
#pragma unroll
            for (int na = 0; na < 4; na++)
#pragma unroll
                for (int h = 0; h < 2; h++)
                    mma16816(acc[m][na * 2 + h], ah, &blo[na][h * 2]);
#pragma unroll
            for (int na = 0; na < 4; na++)
#pragma unroll
                for (int h = 0; h < 2; h++)
                    mma16816(acc[m][na * 2 + h], al, &bhi[na][h * 2]);
        }
    }

#pragma unroll
    for (int m = 0; m < 4; m++) {
        int row = bm + warpM + m * 16 + (lane >> 2);
#pragma unroll
        for (int n = 0; n < 8; n++) {
            int col = bn + warpN + n * 8 + (lane & 3) * 2;
            *(float2*)(g_z + (size_t)row * OUT_DIM + col) =
                make_float2(acc[m][n][0], acc[m][n][1]);
            *(float2*)(g_z + (size_t)(row + 8) * OUT_DIM + col) =
                make_float2(acc[m][n][2], acc[m][n][3]);
        }
    }
}

// ---------------------------------------------------------------------------
// Batched QR of 256x3 via CholQR + LAPACK Householder sign reconstruction.
// One warp per batch row; lane l owns rows 8l..8l+7 (coalesced float4 I/O).
//  1. G = M^T M  (6 dots, one ILP'd warp-reduction batch)
//  2. Cholesky G = U^T U (scalar 3x3, all lanes redundantly)
//  3. Reconstruct Householder pivot signs s_k = -sign(alpha_k) from the top
//     3x3 block of M + G (reflector dots collapse to Gram entries).
//  4. Q = M * R^{-1},  R = diag(s) * U
// ---------------------------------------------------------------------------
__global__ __launch_bounds__(256) void qr_kernel(float* __restrict__ out) {
    const int warp = (blockIdx.x * blockDim.x + threadIdx.x) >> 5;
    const int lane = threadIdx.x & 31;
    if (warp >= B_ROWS) return;

    float4 buf[6];
    const float4* zp = (const float4*)(g_z + (size_t)warp * OUT_DIM) + lane * 6;
#pragma unroll
    for (int i = 0; i < 6; i++) buf[i] = zp[i];
    float* bf = (float*)buf;

    float Mv[8][3];
#pragma unroll
    for (int r = 0; r < 8; r++)
#pragma unroll
        for (int j = 0; j < 3; j++) Mv[r][j] = bf[r * 3 + j];

    // --- 1. Gram matrix: 6 independent reductions, interleaved shfl chains ---
    float g00 = 0.f, g01 = 0.f, g02 = 0.f, g11 = 0.f, g12 = 0.f, g22 = 0.f;
#pragma unroll
    for (int r = 0; r < 8; r++) {
        float a = Mv[r][0], b = Mv[r][1], c = Mv[r][2];
        g00 = fmaf(a, a, g00); g01 = fmaf(a, b, g01); g02 = fmaf(a, c, g02);
        g11 = fmaf(b, b, g11); g12 = fmaf(b, c, g12); g22 = fmaf(c, c, g22);
    }
#pragma unroll
    for (int o = 16; o > 0; o >>= 1) {
        g00 += __shfl_xor_sync(0xffffffffu, g00, o);
        g01 += __shfl_xor_sync(0xffffffffu, g01, o);
        g02 += __shfl_xor_sync(0xffffffffu, g02, o);
        g11 += __shfl_xor_sync(0xffffffffu, g11, o);
        g12 += __shfl_xor_sync(0xffffffffu, g12, o);
        g22 += __shfl_xor_sync(0xffffffffu, g22, o);
    }

    // --- broadcast top 3x3 of M from lane 0 (rows 0..2 live there) ---
    float M00 = __shfl_sync(0xffffffffu, Mv[0][0], 0);
    float M01 = __shfl_sync(0xffffffffu, Mv[0][1], 0);
    float M02 = __shfl_sync(0xffffffffu, Mv[0][2], 0);
    float M10 = __shfl_sync(0xffffffffu, Mv[1][0], 0);
    float M11 = __shfl_sync(0xffffffffu, Mv[1][1], 0);
    float M12 = __shfl_sync(0xffffffffu, Mv[1][2], 0);
    float M20 = __shfl_sync(0xffffffffu, Mv[2][0], 0);
    float M21 = __shfl_sync(0xffffffffu, Mv[2][1], 0);
    float M22 = __shfl_sync(0xffffffffu, Mv[2][2], 0);

    // --- 2. Cholesky of G (U upper triangular, positive diagonal) ---
    float u00 = sqrtf(g00);
    float u01 = g01 / u00;
    float u02 = g02 / u00;
    float u11 = sqrtf(g11 - u01 * u01);
    float u12 = (g12 - u01 * u02) / u11;
    float u22 = sqrtf(g22 - u02 * u02 - u12 * u12);

    // --- 3. Householder pivot signs (beta_k = -sign(alpha_k)*nrm) ---
    // k = 0
    float s0 = (M00 >= 0.f) ? -1.f : 1.f;
    float beta0 = s0 * u00;
    float c0 = M00 - beta0;                 // |c0| >= u00 > 0
    float tau0 = (beta0 - M00) / beta0;
    float v01 = M10 / c0, v02 = M20 / c0;   // Householder v entries rows 1,2
    float w1 = M01 + (g01 - M00 * M01) / c0;   // v^T M[:,1]
    float w2 = M02 + (g02 - M00 * M02) / c0;   // v^T M[:,2]
    // k = 1: pivot after H0
    float alpha1 = M11 - tau0 * v01 * w1;
    float s1 = (alpha1 >= 0.f) ? -1.f : 1.f;
    float beta1 = s1 * u11;
    float c1 = alpha1 - beta1;              // |c1| >= u11 > 0
    float tau1 = (beta1 - alpha1) / beta1;
    // k = 2: pivot after H1 H0
    float a12 = M12 - tau0 * v01 * w2;      // (H0 M)[1][2]
    float a21 = M21 - tau0 * v02 * w1;      // (H0 M)[2][1]
    float a22 = M22 - tau0 * v02 * w2;      // (H0 M)[2][2]
    float R01 = s0 * u01, R02 = s0 * u02;
    float K12 = g12 - R01 * R02;            // (H0M)[1:,1]^T (H0M)[1:,2]
    float w22 = a12 + (K12 - alpha1 * a12) / c1;  // v1^T (H0M)[1:,2]
    float alpha2 = a22 - tau1 * (a21 / c1) * w22;
    float s2 = (alpha2 >= 0.f) ? -1.f : 1.f;

    // --- 4. Rinv for R = diag(s)*U, then Q = M * Rinv ---
    float R11 = s1 * u11, R12 = s1 * u12;
    float i00 = s0 / u00;
    float i11 = s1 / u11;
    float i22 = s2 / u22;
    float i01 = -R01 * i00 * i11;
    float i12 = -R12 * i11 * i22;
    float i02 = (R01 * R12 - R02 * R11) * i00 * i11 * i22;

#pragma unroll
    for (int r = 0; r < 8; r++) {
        float m0 = Mv[r][0], m1 = Mv[r][1], m2 = Mv[r][2];
        bf[r * 3 + 0] = m0 * i00;
        bf[r * 3 + 1] = fmaf(m0, i01, m1 * i11);
        bf[r * 3 + 2] = fmaf(m0, i02, fmaf(m1, i12, m2 * i22));
    }
    float4* op = (float4*)(out + (size_t)warp * OUT_DIM) + lane * 6;
#pragma unroll
    for (int i = 0; i < 6; i++) op[i] = buf[i];
}

// ---------------------------------------------------------------------------
// kernel_launch: ONLY kernel launches — no runtime API calls of any kind.
// ---------------------------------------------------------------------------
extern "C" void kernel_launch(void* const* d_in, const int* in_sizes, int n_in,
                              void* d_out, int out_size) {
    const float* x = (const float*)d_in[0];   // (16384, 1024) fp32
    const float* W = (const float*)d_in[1];   // (768, 1024) fp32
    float* out = (float*)d_out;               // (16384, 768) fp32

    split_all_kernel<<<(N4X + N4W + 255) / 256, 256>>>(x, W);

    dim3 grid(OUT_DIM / 128, B_ROWS / 128);   // (6, 128)
    gemm_bf16x3_kernel<<<grid, 128, SMEM_DYN>>>();

    qr_kernel<<<2048, 256>>>(out);
}